// round 15
// baseline (speedup 1.0000x reference)
#include <cuda_runtime.h>
#include <cuda_bf16.h>
#include <cstdint>

#define NROWS 8192
#define DIM   128
#define CHUNK 128                  // samples per tile
#define NBLOCKS 128                // b<64: X chunk b (+diag); b>=64: Y chunk b-64
#define NTHREADS 512               // 16 warps
#define NPART 64                   // partials per matrix
#define NELEM4 4096                // DIM*DIM/4 float4 elements per partial
#define FIN_BLOCKS 64

// ---------------- device-global scratch (no allocations allowed) -----------
// g_part[m][i] = block i's raw partial of P_m = H^T H + 2 H^T L (8 MB total).
// Fully overwritten every launch -> no zeroing pass needed.
__device__ float    g_part[2][NPART][DIM * DIM];
__device__ float    g_S1;               // <Px,Py>_F accumulator
__device__ float    g_S2;               // sum d_i^2
__device__ float    g_S3;               // sum d_i
__device__ unsigned g_ticket;

// ---------------- helpers ---------------------------------------------------
__device__ __forceinline__ uint32_t smem_u32(const void* p) {
    uint32_t a;
    asm("{ .reg .u64 t; cvta.to.shared.u64 t, %1; cvt.u32.u64 %0, t; }" : "=r"(a) : "l"(p));
    return a;
}

// Tile stored SAMPLE-major: S[k][d]; two 16KB subtiles by d>>6; SW128 swizzle.
__device__ __forceinline__ uint32_t toff(int k, int d) {
    uint32_t o = (uint32_t)(k * 128 + (d & 63) * 2);
    o ^= (o >> 3) & 0x70;
    return (uint32_t)((d >> 6) * 16384) + o;
}

#define LO_OFF     32768           // 2*lo tile after hi tile (each 32KB)
#define SMEM_TOTAL 65536

__device__ __forceinline__ void ldsm4t(uint32_t* r, uint32_t addr) {
    asm volatile("ldmatrix.sync.aligned.m8n8.x4.trans.shared.b16 {%0,%1,%2,%3}, [%4];"
                 : "=r"(r[0]), "=r"(r[1]), "=r"(r[2]), "=r"(r[3]) : "r"(addr));
}

__device__ __forceinline__ void mma_bf16(float* d, const uint32_t* a,
                                         uint32_t b0, uint32_t b1) {
    asm volatile(
        "mma.sync.aligned.m16n8k16.row.col.f32.bf16.bf16.f32 "
        "{%0,%1,%2,%3}, {%4,%5,%6,%7}, {%8,%9}, {%0,%1,%2,%3};"
        : "+f"(d[0]), "+f"(d[1]), "+f"(d[2]), "+f"(d[3])
        : "r"(a[0]), "r"(a[1]), "r"(a[2]), "r"(a[3]), "r"(b0), "r"(b1));
}

// ---------------------------------------------------------------------------
// Kernel 1: convert(+diag) -> tensor-core P = H^T H + H^T(2L) -> STG partial.
// (Unchanged: measured ~7.4us.)
// ---------------------------------------------------------------------------
__global__ __launch_bounds__(NTHREADS, 1)
void gram_diag(const float* __restrict__ X, const float* __restrict__ Y) {
    extern __shared__ char smem[];
    const uint32_t sb = smem_u32(smem);
    const int tid  = threadIdx.x;
    const int w    = tid >> 5;
    const int lane = tid & 31;

    const bool isX  = blockIdx.x < (NBLOCKS / 2);
    const int chunk = isX ? blockIdx.x : blockIdx.x - NBLOCKS / 2;
    const float* base  = (isX ? X : Y) + (size_t)chunk * CHUNK * DIM;
    const float* ybase = Y + (size_t)chunk * CHUNK * DIM;   // diag (X blocks)

    // ldmatrix per-lane tile-row selectors
    const int lr    = lane & 7;
    const int a_kad = (lane & 16) ? 8 : 0;
    const int a_mad = (lane & 8)  ? 8 : 0;
    const int b_kad = (lane & 8)  ? 8 : 0;
    const int b_nad = (lane & 16) ? 8 : 0;
    const int m0    = (w & 7) * 16;        // warp's output row slab
    const int nbase = (w >> 3) * 64;       // warp's output column half

    // ---- convert fp32 -> bf16 hi and 2*lo tiles; X blocks also do diag ----
    float s2 = 0.0f, s3 = 0.0f;
    #pragma unroll
    for (int it = 0; it < 8; ++it) {
        const int r = w + 16 * it;                    // sample row
        const float4 v = *reinterpret_cast<const float4*>(base + r * DIM + lane * 4);
        __nv_bfloat162 h01 = __floats2bfloat162_rn(v.x, v.y);
        __nv_bfloat162 h23 = __floats2bfloat162_rn(v.z, v.w);
        __nv_bfloat162 l01 = __floats2bfloat162_rn(2.0f * (v.x - __bfloat162float(h01.x)),
                                                   2.0f * (v.y - __bfloat162float(h01.y)));
        __nv_bfloat162 l23 = __floats2bfloat162_rn(2.0f * (v.z - __bfloat162float(h23.x)),
                                                   2.0f * (v.w - __bfloat162float(h23.y)));
        const uint32_t o = toff(r, lane * 4);
        uint2 hv, lv;
        hv.x = *reinterpret_cast<uint32_t*>(&h01);
        hv.y = *reinterpret_cast<uint32_t*>(&h23);
        lv.x = *reinterpret_cast<uint32_t*>(&l01);
        lv.y = *reinterpret_cast<uint32_t*>(&l23);
        *reinterpret_cast<uint2*>(smem + o)          = hv;
        *reinterpret_cast<uint2*>(smem + LO_OFF + o) = lv;

        if (isX) {                                    // diag: d_r = <x_r, y_r>
            const float4 u = *reinterpret_cast<const float4*>(ybase + r * DIM + lane * 4);
            float d = v.x * u.x + v.y * u.y + v.z * u.z + v.w * u.w;
            #pragma unroll
            for (int o2 = 16; o2; o2 >>= 1) d += __shfl_xor_sync(0xffffffffu, d, o2);
            s3 += d;
            s2 += d * d;
        }
    }
    if (isX && lane == 0) {
        atomicAdd(&g_S3, s3);
        atomicAdd(&g_S2, s2);
    }
    __syncthreads();

    // ---- MMA mainloop: P = H^T H + H^T(2L); A-frags hi only ----
    float acc[8][4];
    #pragma unroll
    for (int nt = 0; nt < 8; ++nt)
        #pragma unroll
        for (int i = 0; i < 4; ++i) acc[nt][i] = 0.0f;

    for (int ks = 0; ks < 8; ++ks) {
        const int k0 = ks * 16;
        uint32_t ahi[4];
        ldsm4t(ahi, sb + toff(k0 + lr + a_kad, m0 + a_mad));

        #pragma unroll
        for (int ntp = 0; ntp < 4; ++ntp) {
            const int n0 = nbase + ntp * 16;
            uint32_t bhi[4], blo[4];
            const uint32_t boff = toff(k0 + lr + b_kad, n0 + b_nad);
            ldsm4t(bhi, sb + boff);
            ldsm4t(blo, sb + LO_OFF + boff);
            mma_bf16(acc[2 * ntp],     ahi, bhi[0], bhi[1]);
            mma_bf16(acc[2 * ntp],     ahi, blo[0], blo[1]);
            mma_bf16(acc[2 * ntp + 1], ahi, bhi[2], bhi[3]);
            mma_bf16(acc[2 * ntp + 1], ahi, blo[2], blo[3]);
        }
    }

    // ---- store partial P with plain STG.64 (private slice; no atomics) ----
    float* P = g_part[isX ? 0 : 1][chunk];
    const int row0 = m0 + (lane >> 2);
    const int col0 = (lane & 3) * 2;
    #pragma unroll
    for (int nt = 0; nt < 8; ++nt) {
        const int cc = nbase + nt * 8 + col0;
        *reinterpret_cast<float2*>(&P[row0 * DIM + cc]) =
            make_float2(acc[nt][0], acc[nt][1]);
        *reinterpret_cast<float2*>(&P[(row0 + 8) * DIM + cc]) =
            make_float2(acc[nt][2], acc[nt][3]);
    }
}

// ---------------------------------------------------------------------------
// Kernel 2: 64 blocks x 1024. Thread (el, g): sum 4 partials (float4) of both
// matrices (8 independent loads, fully reg-batchable); smem combine over 16
// groups; dot; 2-warp reduce; ticket-last combines + resets scalars.
// 64K threads x 128B = 8MB in flight -> covers DRAM/L2 latency.
// ---------------------------------------------------------------------------
__global__ __launch_bounds__(1024, 1)
void finalize(float* __restrict__ out) {
    __shared__ float4 sxs[16][64];
    __shared__ float4 sys[16][64];
    __shared__ float  wsum[2];
    const int tid = threadIdx.x;
    const int el  = tid & 63;               // element slot within block
    const int g   = tid >> 6;               // partial group (0..15), 4 partials each
    const int e4  = blockIdx.x * 64 + el;   // global float4 index (4096 total)

    const float4* Px = reinterpret_cast<const float4*>(g_part[0]) + (size_t)g * 4 * NELEM4 + e4;
    const float4* Py = reinterpret_cast<const float4*>(g_part[1]) + (size_t)g * 4 * NELEM4 + e4;

    float4 sx = make_float4(0.f, 0.f, 0.f, 0.f);
    float4 sy = make_float4(0.f, 0.f, 0.f, 0.f);
    #pragma unroll
    for (int i = 0; i < 4; ++i) {
        const float4 a = Px[(size_t)i * NELEM4];
        const float4 b = Py[(size_t)i * NELEM4];
        sx.x += a.x; sx.y += a.y; sx.z += a.z; sx.w += a.w;
        sy.x += b.x; sy.y += b.y; sy.z += b.z; sy.w += b.w;
    }
    sxs[g][el] = sx;
    sys[g][el] = sy;
    __syncthreads();

    if (g == 0) {                            // threads 0..63 (2 warps)
        float ax = sx.x, ay = sx.y, az = sx.z, aw = sx.w;
        float bx = sy.x, by = sy.y, bz = sy.z, bw = sy.w;
        #pragma unroll
        for (int k = 1; k < 16; ++k) {
            const float4 xk = sxs[k][el], yk = sys[k][el];
            ax += xk.x; ay += xk.y; az += xk.z; aw += xk.w;
            bx += yk.x; by += yk.y; bz += yk.z; bw += yk.w;
        }
        float s1 = ax * bx + ay * by + az * bz + aw * bw;
        const int lane = tid & 31;
        #pragma unroll
        for (int o = 16; o; o >>= 1) s1 += __shfl_xor_sync(0xffffffffu, s1, o);
        if (lane == 0) wsum[tid >> 5] = s1;
    }
    __syncthreads();

    if (tid == 0) {
        atomicAdd(&g_S1, wsum[0] + wsum[1]);
        __threadfence();
        const unsigned last = atomicAdd(&g_ticket, 1u);
        if (last == FIN_BLOCKS - 1) {
            const float S1 = atomicAdd(&g_S1, 0.0f);   // coherent read
            const double loss =
                ((double)S1 - (double)g_S2) / ((double)NROWS * (double)(NROWS - 1))
                - 2.0 * (double)g_S3 / (double)NROWS;
            out[0] = (float)loss;
            g_S1 = 0.0f; g_S2 = 0.0f; g_S3 = 0.0f; g_ticket = 0u;
        }
    }
}

// ---------------------------------------------------------------------------
extern "C" void kernel_launch(void* const* d_in, const int* in_sizes, int n_in,
                              void* d_out, int out_size) {
    const float* X = (const float*)d_in[0];
    const float* Y = (const float*)d_in[1];
    float* out = (float*)d_out;

    static bool attr_set = false;   // idempotent host-side attribute
    if (!attr_set) {
        cudaFuncSetAttribute(gram_diag,
                             cudaFuncAttributeMaxDynamicSharedMemorySize, SMEM_TOTAL);
        attr_set = true;
    }

    gram_diag<<<NBLOCKS, NTHREADS, SMEM_TOTAL>>>(X, Y);
    finalize<<<FIN_BLOCKS, 1024>>>(out);
}

// round 16
// speedup vs baseline: 1.1356x; 1.1356x over previous
#include <cuda_runtime.h>
#include <cuda_bf16.h>
#include <cstdint>

#define NROWS 8192
#define DIM   128
#define CHUNK 128                  // samples per tile
#define NBLOCKS 128                // b<64: X chunk b; b>=64: Y chunk b-64
#define NTHREADS 512               // 16 warps
#define NPART 64                   // partials per matrix
#define NELEM4 4096                // DIM*DIM/4 float4 elements per partial
#define FIN_BLOCKS 128

// ---------------- device-global scratch (no allocations allowed) -----------
// g_part[m][i] = block i's raw partial of P_m = H^T H + 2 H^T L (8 MB total).
// Fully overwritten every launch -> no zeroing pass needed.
__device__ float    g_part[2][NPART][DIM * DIM];
__device__ float    g_S1;               // <Px,Py>_F accumulator
__device__ float    g_S2;               // sum d_i^2
__device__ float    g_S3;               // sum d_i
__device__ unsigned g_ticket;

// ---------------- helpers ---------------------------------------------------
__device__ __forceinline__ uint32_t smem_u32(const void* p) {
    uint32_t a;
    asm("{ .reg .u64 t; cvta.to.shared.u64 t, %1; cvt.u32.u64 %0, t; }" : "=r"(a) : "l"(p));
    return a;
}

// Tile stored SAMPLE-major: S[k][d]; two 16KB subtiles by d>>6; SW128 swizzle.
__device__ __forceinline__ uint32_t toff(int k, int d) {
    uint32_t o = (uint32_t)(k * 128 + (d & 63) * 2);
    o ^= (o >> 3) & 0x70;
    return (uint32_t)((d >> 6) * 16384) + o;
}

#define LO_OFF     32768           // 2*lo tile after hi tile (each 32KB)
#define SMEM_TOTAL 65536

__device__ __forceinline__ void ldsm4t(uint32_t* r, uint32_t addr) {
    asm volatile("ldmatrix.sync.aligned.m8n8.x4.trans.shared.b16 {%0,%1,%2,%3}, [%4];"
                 : "=r"(r[0]), "=r"(r[1]), "=r"(r[2]), "=r"(r[3]) : "r"(addr));
}

__device__ __forceinline__ void mma_bf16(float* d, const uint32_t* a,
                                         uint32_t b0, uint32_t b1) {
    asm volatile(
        "mma.sync.aligned.m16n8k16.row.col.f32.bf16.bf16.f32 "
        "{%0,%1,%2,%3}, {%4,%5,%6,%7}, {%8,%9}, {%0,%1,%2,%3};"
        : "+f"(d[0]), "+f"(d[1]), "+f"(d[2]), "+f"(d[3])
        : "r"(a[0]), "r"(a[1]), "r"(a[2]), "r"(a[3]), "r"(b0), "r"(b1));
}

// ---------------------------------------------------------------------------
// Kernel 1: convert(+balanced diag) -> tensor-core P -> STG partial.
// Diag split: X blocks reduce rows <64, Y blocks rows >=64 of their chunk.
// ---------------------------------------------------------------------------
__global__ __launch_bounds__(NTHREADS, 1)
void gram_diag(const float* __restrict__ X, const float* __restrict__ Y) {
    extern __shared__ char smem[];
    const uint32_t sb = smem_u32(smem);
    const int tid  = threadIdx.x;
    const int w    = tid >> 5;
    const int lane = tid & 31;

    const bool isX  = blockIdx.x < (NBLOCKS / 2);
    const int chunk = isX ? blockIdx.x : blockIdx.x - NBLOCKS / 2;
    const float* base  = (isX ? X : Y) + (size_t)chunk * CHUNK * DIM;
    const float* other = (isX ? Y : X) + (size_t)chunk * CHUNK * DIM; // diag partner

    // ldmatrix per-lane tile-row selectors
    const int lr    = lane & 7;
    const int a_kad = (lane & 16) ? 8 : 0;
    const int a_mad = (lane & 8)  ? 8 : 0;
    const int b_kad = (lane & 8)  ? 8 : 0;
    const int b_nad = (lane & 16) ? 8 : 0;
    const int m0    = (w & 7) * 16;        // warp's output row slab
    const int nbase = (w >> 3) * 64;       // warp's output column half

    // ---- convert fp32 -> bf16 hi and 2*lo tiles; balanced diag ----
    float s2 = 0.0f, s3 = 0.0f;
    #pragma unroll
    for (int it = 0; it < 8; ++it) {
        const int r = w + 16 * it;                    // sample row
        const float4 v = *reinterpret_cast<const float4*>(base + r * DIM + lane * 4);
        __nv_bfloat162 h01 = __floats2bfloat162_rn(v.x, v.y);
        __nv_bfloat162 h23 = __floats2bfloat162_rn(v.z, v.w);
        __nv_bfloat162 l01 = __floats2bfloat162_rn(2.0f * (v.x - __bfloat162float(h01.x)),
                                                   2.0f * (v.y - __bfloat162float(h01.y)));
        __nv_bfloat162 l23 = __floats2bfloat162_rn(2.0f * (v.z - __bfloat162float(h23.x)),
                                                   2.0f * (v.w - __bfloat162float(h23.y)));
        const uint32_t o = toff(r, lane * 4);
        uint2 hv, lv;
        hv.x = *reinterpret_cast<uint32_t*>(&h01);
        hv.y = *reinterpret_cast<uint32_t*>(&h23);
        lv.x = *reinterpret_cast<uint32_t*>(&l01);
        lv.y = *reinterpret_cast<uint32_t*>(&l23);
        *reinterpret_cast<uint2*>(smem + o)          = hv;
        *reinterpret_cast<uint2*>(smem + LO_OFF + o) = lv;

        // balanced diag: X blocks own rows <64, Y blocks own rows >=64
        if (isX ? (r < 64) : (r >= 64)) {             // uniform per warp-iter
            const float4 u = *reinterpret_cast<const float4*>(other + r * DIM + lane * 4);
            float d = v.x * u.x + v.y * u.y + v.z * u.z + v.w * u.w;
            #pragma unroll
            for (int o2 = 16; o2; o2 >>= 1) d += __shfl_xor_sync(0xffffffffu, d, o2);
            s3 += d;
            s2 += d * d;
        }
    }
    if (lane == 0) {
        atomicAdd(&g_S3, s3);
        atomicAdd(&g_S2, s2);
    }
    __syncthreads();

    // ---- MMA mainloop: P = H^T H + H^T(2L); A-frags hi only ----
    float acc[8][4];
    #pragma unroll
    for (int nt = 0; nt < 8; ++nt)
        #pragma unroll
        for (int i = 0; i < 4; ++i) acc[nt][i] = 0.0f;

    for (int ks = 0; ks < 8; ++ks) {
        const int k0 = ks * 16;
        uint32_t ahi[4];
        ldsm4t(ahi, sb + toff(k0 + lr + a_kad, m0 + a_mad));

        #pragma unroll
        for (int ntp = 0; ntp < 4; ++ntp) {
            const int n0 = nbase + ntp * 16;
            uint32_t bhi[4], blo[4];
            const uint32_t boff = toff(k0 + lr + b_kad, n0 + b_nad);
            ldsm4t(bhi, sb + boff);
            ldsm4t(blo, sb + LO_OFF + boff);
            mma_bf16(acc[2 * ntp],     ahi, bhi[0], bhi[1]);
            mma_bf16(acc[2 * ntp],     ahi, blo[0], blo[1]);
            mma_bf16(acc[2 * ntp + 1], ahi, bhi[2], bhi[3]);
            mma_bf16(acc[2 * ntp + 1], ahi, blo[2], blo[3]);
        }
    }

    // ---- store partial P with plain STG.64 (private slice; no atomics) ----
    float* P = g_part[isX ? 0 : 1][chunk];
    const int row0 = m0 + (lane >> 2);
    const int col0 = (lane & 3) * 2;
    #pragma unroll
    for (int nt = 0; nt < 8; ++nt) {
        const int cc = nbase + nt * 8 + col0;
        *reinterpret_cast<float2*>(&P[row0 * DIM + cc]) =
            make_float2(acc[nt][0], acc[nt][1]);
        *reinterpret_cast<float2*>(&P[(row0 + 8) * DIM + cc]) =
            make_float2(acc[nt][2], acc[nt][3]);
    }
}

// ---------------------------------------------------------------------------
// Kernel 2: 128 blocks x 512. Thread (el, g): sum 4 partials (float4) of both
// matrices (8 loads, reg-batchable); smem combine over 16 groups; dot; 1-warp
// reduce; ticket-last combines + resets scalars. Spans 128 SMs.
// ---------------------------------------------------------------------------
__global__ __launch_bounds__(512, 1)
void finalize(float* __restrict__ out) {
    __shared__ float4 sxs[16][32];
    __shared__ float4 sys[16][32];
    const int tid = threadIdx.x;
    const int el  = tid & 31;               // element slot within block
    const int g   = tid >> 5;               // partial group (0..15), 4 partials each
    const int e4  = blockIdx.x * 32 + el;   // global float4 index (4096 total)

    const float4* Px = reinterpret_cast<const float4*>(g_part[0]) + (size_t)g * 4 * NELEM4 + e4;
    const float4* Py = reinterpret_cast<const float4*>(g_part[1]) + (size_t)g * 4 * NELEM4 + e4;

    float4 sx = make_float4(0.f, 0.f, 0.f, 0.f);
    float4 sy = make_float4(0.f, 0.f, 0.f, 0.f);
    #pragma unroll
    for (int i = 0; i < 4; ++i) {
        const float4 a = Px[(size_t)i * NELEM4];
        const float4 b = Py[(size_t)i * NELEM4];
        sx.x += a.x; sx.y += a.y; sx.z += a.z; sx.w += a.w;
        sy.x += b.x; sy.y += b.y; sy.z += b.z; sy.w += b.w;
    }
    sxs[g][el] = sx;
    sys[g][el] = sy;
    __syncthreads();

    if (g == 0) {                            // one warp: el == lane
        float ax = sx.x, ay = sx.y, az = sx.z, aw = sx.w;
        float bx = sy.x, by = sy.y, bz = sy.z, bw = sy.w;
        #pragma unroll
        for (int k = 1; k < 16; ++k) {
            const float4 xk = sxs[k][el], yk = sys[k][el];
            ax += xk.x; ay += xk.y; az += xk.z; aw += xk.w;
            bx += yk.x; by += yk.y; bz += yk.z; bw += yk.w;
        }
        float s1 = ax * bx + ay * by + az * bz + aw * bw;
        #pragma unroll
        for (int o = 16; o; o >>= 1) s1 += __shfl_xor_sync(0xffffffffu, s1, o);

        if (el == 0) {
            atomicAdd(&g_S1, s1);
            __threadfence();
            const unsigned last = atomicAdd(&g_ticket, 1u);
            if (last == FIN_BLOCKS - 1) {
                const float S1 = atomicAdd(&g_S1, 0.0f);   // coherent read
                const double loss =
                    ((double)S1 - (double)g_S2) / ((double)NROWS * (double)(NROWS - 1))
                    - 2.0 * (double)g_S3 / (double)NROWS;
                out[0] = (float)loss;
                g_S1 = 0.0f; g_S2 = 0.0f; g_S3 = 0.0f; g_ticket = 0u;
            }
        }
    }
}

// ---------------------------------------------------------------------------
extern "C" void kernel_launch(void* const* d_in, const int* in_sizes, int n_in,
                              void* d_out, int out_size) {
    const float* X = (const float*)d_in[0];
    const float* Y = (const float*)d_in[1];
    float* out = (float*)d_out;

    static bool attr_set = false;   // idempotent host-side attribute
    if (!attr_set) {
        cudaFuncSetAttribute(gram_diag,
                             cudaFuncAttributeMaxDynamicSharedMemorySize, SMEM_TOTAL);
        attr_set = true;
    }

    gram_diag<<<NBLOCKS, NTHREADS, SMEM_TOTAL>>>(X, Y);
    finalize<<<FIN_BLOCKS, 512>>>(out);
}

// round 17
// speedup vs baseline: 1.1552x; 1.0172x over previous
#include <cuda_runtime.h>
#include <cuda_bf16.h>
#include <cstdint>

#define NROWS 8192
#define DIM   128
#define CHUNK 128                  // samples per tile
#define NBLOCKS 128                // b<64: X chunk b; b>=64: Y chunk b-64
#define NTHREADS 512               // 16 warps
#define NPART 64                   // partials per matrix
#define NELEM4 4096                // DIM*DIM/4 float4 elements per partial
#define FIN_BLOCKS 128

// ---------------- device-global scratch (no allocations allowed) -----------
// g_part[m][i] = block i's raw partial of P_m = H^T H + 2 H^T L (8 MB total).
// Fully overwritten every launch -> no zeroing pass needed.
__device__ float    g_part[2][NPART][DIM * DIM];
__device__ float    g_S1;               // <Px,Py>_F accumulator
__device__ float    g_S2;               // sum d_i^2
__device__ float    g_S3;               // sum d_i
__device__ unsigned g_ticket;

// ---------------- helpers ---------------------------------------------------
__device__ __forceinline__ uint32_t smem_u32(const void* p) {
    uint32_t a;
    asm("{ .reg .u64 t; cvta.to.shared.u64 t, %1; cvt.u32.u64 %0, t; }" : "=r"(a) : "l"(p));
    return a;
}

// Tile stored SAMPLE-major: S[k][d]; two 16KB subtiles by d>>6; SW128 swizzle.
__device__ __forceinline__ uint32_t toff(int k, int d) {
    uint32_t o = (uint32_t)(k * 128 + (d & 63) * 2);
    o ^= (o >> 3) & 0x70;
    return (uint32_t)((d >> 6) * 16384) + o;
}

#define LO_OFF     32768           // 2*lo tile after hi tile (each 32KB)
#define SMEM_TOTAL 65536

__device__ __forceinline__ void ldsm4t(uint32_t* r, uint32_t addr) {
    asm volatile("ldmatrix.sync.aligned.m8n8.x4.trans.shared.b16 {%0,%1,%2,%3}, [%4];"
                 : "=r"(r[0]), "=r"(r[1]), "=r"(r[2]), "=r"(r[3]) : "r"(addr));
}

__device__ __forceinline__ void mma_bf16(float* d, const uint32_t* a,
                                         uint32_t b0, uint32_t b1) {
    asm volatile(
        "mma.sync.aligned.m16n8k16.row.col.f32.bf16.bf16.f32 "
        "{%0,%1,%2,%3}, {%4,%5,%6,%7}, {%8,%9}, {%0,%1,%2,%3};"
        : "+f"(d[0]), "+f"(d[1]), "+f"(d[2]), "+f"(d[3])
        : "r"(a[0]), "r"(a[1]), "r"(a[2]), "r"(a[3]), "r"(b0), "r"(b1));
}

// ---------------------------------------------------------------------------
// Kernel 1: convert(+balanced diag) -> tensor-core P -> STG partial.
// Warp tile 32x32: warp w owns rows [(w&3)*32,+32) x cols [(w>>2)*32,+32).
// Per k-step: 2 A-ldsm + 4 B-ldsm feed 16 MMAs (was 9 ldsm for 16).
// ---------------------------------------------------------------------------
__global__ __launch_bounds__(NTHREADS, 1)
void gram_diag(const float* __restrict__ X, const float* __restrict__ Y) {
    extern __shared__ char smem[];
    const uint32_t sb = smem_u32(smem);
    const int tid  = threadIdx.x;
    const int w    = tid >> 5;
    const int lane = tid & 31;

    const bool isX  = blockIdx.x < (NBLOCKS / 2);
    const int chunk = isX ? blockIdx.x : blockIdx.x - NBLOCKS / 2;
    const float* base  = (isX ? X : Y) + (size_t)chunk * CHUNK * DIM;
    const float* other = (isX ? Y : X) + (size_t)chunk * CHUNK * DIM; // diag partner

    // ldmatrix per-lane tile-row selectors
    const int lr    = lane & 7;
    const int a_kad = (lane & 16) ? 8 : 0;
    const int a_mad = (lane & 8)  ? 8 : 0;
    const int b_kad = (lane & 8)  ? 8 : 0;
    const int b_nad = (lane & 16) ? 8 : 0;
    const int m0    = (w & 3) * 32;        // warp's output row slab (32 rows)
    const int nbase = (w >> 2) * 32;       // warp's output col range (32 cols)

    // ---- convert fp32 -> bf16 hi and 2*lo tiles; balanced diag ----
    float s2 = 0.0f, s3 = 0.0f;
    #pragma unroll
    for (int it = 0; it < 8; ++it) {
        const int r = w + 16 * it;                    // sample row
        const float4 v = *reinterpret_cast<const float4*>(base + r * DIM + lane * 4);
        __nv_bfloat162 h01 = __floats2bfloat162_rn(v.x, v.y);
        __nv_bfloat162 h23 = __floats2bfloat162_rn(v.z, v.w);
        __nv_bfloat162 l01 = __floats2bfloat162_rn(2.0f * (v.x - __bfloat162float(h01.x)),
                                                   2.0f * (v.y - __bfloat162float(h01.y)));
        __nv_bfloat162 l23 = __floats2bfloat162_rn(2.0f * (v.z - __bfloat162float(h23.x)),
                                                   2.0f * (v.w - __bfloat162float(h23.y)));
        const uint32_t o = toff(r, lane * 4);
        uint2 hv, lv;
        hv.x = *reinterpret_cast<uint32_t*>(&h01);
        hv.y = *reinterpret_cast<uint32_t*>(&h23);
        lv.x = *reinterpret_cast<uint32_t*>(&l01);
        lv.y = *reinterpret_cast<uint32_t*>(&l23);
        *reinterpret_cast<uint2*>(smem + o)          = hv;
        *reinterpret_cast<uint2*>(smem + LO_OFF + o) = lv;

        // balanced diag: X blocks own rows <64, Y blocks own rows >=64
        if (isX ? (r < 64) : (r >= 64)) {             // uniform per warp-iter
            const float4 u = *reinterpret_cast<const float4*>(other + r * DIM + lane * 4);
            float d = v.x * u.x + v.y * u.y + v.z * u.z + v.w * u.w;
            #pragma unroll
            for (int o2 = 16; o2; o2 >>= 1) d += __shfl_xor_sync(0xffffffffu, d, o2);
            s3 += d;
            s2 += d * d;
        }
    }
    if (lane == 0) {
        atomicAdd(&g_S3, s3);
        atomicAdd(&g_S2, s2);
    }
    __syncthreads();

    // ---- MMA mainloop: P = H^T H + H^T(2L); 32x32 warp tile ----
    // acc[mt*4 + ntp][i]: m-tile mt (0..1, 16 rows), n-tile ntp (0..3, 8 cols)
    float acc[8][4];
    #pragma unroll
    for (int nt = 0; nt < 8; ++nt)
        #pragma unroll
        for (int i = 0; i < 4; ++i) acc[nt][i] = 0.0f;

    for (int ks = 0; ks < 8; ++ks) {
        const int k0 = ks * 16;
        uint32_t ahi0[4], ahi1[4];
        ldsm4t(ahi0, sb + toff(k0 + lr + a_kad, m0 + a_mad));
        ldsm4t(ahi1, sb + toff(k0 + lr + a_kad, m0 + 16 + a_mad));

        #pragma unroll
        for (int half = 0; half < 2; ++half) {
            const int n0 = nbase + half * 16;
            uint32_t bhi[4], blo[4];
            const uint32_t boff = toff(k0 + lr + b_kad, n0 + b_nad);
            ldsm4t(bhi, sb + boff);
            ldsm4t(blo, sb + LO_OFF + boff);
            const int nt0 = 2 * half;
            mma_bf16(acc[nt0],         ahi0, bhi[0], bhi[1]);
            mma_bf16(acc[nt0],         ahi0, blo[0], blo[1]);
            mma_bf16(acc[nt0 + 1],     ahi0, bhi[2], bhi[3]);
            mma_bf16(acc[nt0 + 1],     ahi0, blo[2], blo[3]);
            mma_bf16(acc[4 + nt0],     ahi1, bhi[0], bhi[1]);
            mma_bf16(acc[4 + nt0],     ahi1, blo[0], blo[1]);
            mma_bf16(acc[4 + nt0 + 1], ahi1, bhi[2], bhi[3]);
            mma_bf16(acc[4 + nt0 + 1], ahi1, blo[2], blo[3]);
        }
    }

    // ---- store partial P with plain STG.64 (private slice; no atomics) ----
    float* P = g_part[isX ? 0 : 1][chunk];
    const int rbase = m0 + (lane >> 2);
    const int col0  = (lane & 3) * 2;
    #pragma unroll
    for (int mt = 0; mt < 2; ++mt) {
        const int rr = rbase + mt * 16;
        #pragma unroll
        for (int ntp = 0; ntp < 4; ++ntp) {
            const int cc = nbase + ntp * 8 + col0;
            const float* a = acc[mt * 4 + ntp];
            *reinterpret_cast<float2*>(&P[rr * DIM + cc])       = make_float2(a[0], a[1]);
            *reinterpret_cast<float2*>(&P[(rr + 8) * DIM + cc]) = make_float2(a[2], a[3]);
        }
    }
}

// ---------------------------------------------------------------------------
// Kernel 2: 128 blocks x 512. Thread (el, g): sum 4 partials (float4) of both
// matrices (8 loads, reg-batchable); smem combine over 16 groups; dot; 1-warp
// reduce; ticket-last combines + resets scalars. Spans 128 SMs.
// ---------------------------------------------------------------------------
__global__ __launch_bounds__(512, 1)
void finalize(float* __restrict__ out) {
    __shared__ float4 sxs[16][32];
    __shared__ float4 sys[16][32];
    const int tid = threadIdx.x;
    const int el  = tid & 31;               // element slot within block
    const int g   = tid >> 5;               // partial group (0..15), 4 partials each
    const int e4  = blockIdx.x * 32 + el;   // global float4 index (4096 total)

    const float4* Px = reinterpret_cast<const float4*>(g_part[0]) + (size_t)g * 4 * NELEM4 + e4;
    const float4* Py = reinterpret_cast<const float4*>(g_part[1]) + (size_t)g * 4 * NELEM4 + e4;

    float4 sx = make_float4(0.f, 0.f, 0.f, 0.f);
    float4 sy = make_float4(0.f, 0.f, 0.f, 0.f);
    #pragma unroll
    for (int i = 0; i < 4; ++i) {
        const float4 a = Px[(size_t)i * NELEM4];
        const float4 b = Py[(size_t)i * NELEM4];
        sx.x += a.x; sx.y += a.y; sx.z += a.z; sx.w += a.w;
        sy.x += b.x; sy.y += b.y; sy.z += b.z; sy.w += b.w;
    }
    sxs[g][el] = sx;
    sys[g][el] = sy;
    __syncthreads();

    if (g == 0) {                            // one warp: el == lane
        float ax = sx.x, ay = sx.y, az = sx.z, aw = sx.w;
        float bx = sy.x, by = sy.y, bz = sy.z, bw = sy.w;
        #pragma unroll
        for (int k = 1; k < 16; ++k) {
            const float4 xk = sxs[k][el], yk = sys[k][el];
            ax += xk.x; ay += xk.y; az += xk.z; aw += xk.w;
            bx += yk.x; by += yk.y; bz += yk.z; bw += yk.w;
        }
        float s1 = ax * bx + ay * by + az * bz + aw * bw;
        #pragma unroll
        for (int o = 16; o; o >>= 1) s1 += __shfl_xor_sync(0xffffffffu, s1, o);

        if (el == 0) {
            atomicAdd(&g_S1, s1);
            __threadfence();
            const unsigned last = atomicAdd(&g_ticket, 1u);
            if (last == FIN_BLOCKS - 1) {
                const float S1 = atomicAdd(&g_S1, 0.0f);   // coherent read
                const double loss =
                    ((double)S1 - (double)g_S2) / ((double)NROWS * (double)(NROWS - 1))
                    - 2.0 * (double)g_S3 / (double)NROWS;
                out[0] = (float)loss;
                g_S1 = 0.0f; g_S2 = 0.0f; g_S3 = 0.0f; g_ticket = 0u;
            }
        }
    }
}

// ---------------------------------------------------------------------------
extern "C" void kernel_launch(void* const* d_in, const int* in_sizes, int n_in,
                              void* d_out, int out_size) {
    const float* X = (const float*)d_in[0];
    const float* Y = (const float*)d_in[1];
    float* out = (float*)d_out;

    static bool attr_set = false;   // idempotent host-side attribute
    if (!attr_set) {
        cudaFuncSetAttribute(gram_diag,
                             cudaFuncAttributeMaxDynamicSharedMemorySize, SMEM_TOTAL);
        attr_set = true;
    }

    gram_diag<<<NBLOCKS, NTHREADS, SMEM_TOTAL>>>(X, Y);
    finalize<<<FIN_BLOCKS, 512>>>(out);
}